// round 12
// baseline (speedup 1.0000x reference)
#include <cuda_runtime.h>
#include <cuda_bf16.h>
#include <stdint.h>

// Canny NMS, collapsed conv form — vertical register-march, v2.
// Interior chunks take a clamp-free fast path (no row bounds logic, incremental
// offsets); only the first/last row-chunks run the clamped slow path.
//   idx = floor(ori/45)&7;  fwd = nb[idx], bwd = nb[idx^4] via 8-SEL tree
//   pos = m + bias[idx] - fwd;  neg = m + bias[idx^4] - bwd
//   out = (min(pos,neg) > 0) ? m : 0      (zero windows = SAME padding)

#define IMG_H 4096
#define IMG_W 4096
#define FULLMASK 0xFFFFFFFFu
#define H 28                 // rows per warp chunk
#define STRIPS 32            // 4096 / 128
#define GRIDB 588            // (32 strips * 147 chunks) / 8 warps per block

__device__ __forceinline__ void extend6(float* dst, float4 v, float lv, float rv,
                                        bool lane0, bool lane31)
{
    const float su = __shfl_up_sync(FULLMASK, v.w, 1);
    const float sd = __shfl_down_sync(FULLMASK, v.x, 1);
    dst[0] = lane0 ? lv : su;
    dst[1] = v.x; dst[2] = v.y; dst[3] = v.z; dst[4] = v.w;
    dst[5] = lane31 ? rv : sd;
}

__device__ __forceinline__ float4 nms_row(
    const float (&U)[6], const float (&C)[6], const float (&D)[6],
    float4 O4, const float* sbias)
{
    const float Oa[4] = { O4.x, O4.y, O4.z, O4.w };
    float R[4];
#pragma unroll
    for (int i = 0; i < 4; i++) {
        const int idx = ((int)(Oa[i] * (1.0f / 45.0f))) & 7;
        const bool b0 = (idx & 1);
        const bool b1 = (idx & 2);
        const bool b2 = (idx & 4);
        // k0:C[i+2] k1:D[i+2] k2:D[i+1] k3:D[i] k4:C[i] k5:U[i] k6:U[i+1] k7:U[i+2]
        const float a0  = b0 ? D[i + 2] : C[i + 2];
        const float a1  = b0 ? D[i]     : D[i + 1];
        const float s_l = b1 ? a1 : a0;               // nb[idx & 3]
        const float h0  = b0 ? U[i]     : C[i];
        const float h1  = b0 ? U[i + 2] : U[i + 1];
        const float s_h = b1 ? h1 : h0;               // nb[(idx & 3) | 4]
        const float fwd = b2 ? s_h : s_l;             // nb[idx]
        const float bwd = b2 ? s_l : s_h;             // nb[idx ^ 4]
        const float m   = C[i + 1];
        const float pos = (m - fwd) + sbias[idx];
        const float neg = (m - bwd) + sbias[idx ^ 4];
        R[i] = (fminf(pos, neg) > 0.0f) ? m : 0.0f;
    }
    return make_float4(R[0], R[1], R[2], R[3]);
}

// fast path: all touched rows (r0-1 .. r0+H+1) strictly inside the image
__device__ __forceinline__ void march_fast(
    const float* __restrict__ mag, const float* __restrict__ ori,
    float* __restrict__ out, const float* sbias,
    int r0, int x, int xl, int xr, float lmask, float rmask,
    bool lane0, bool lane31)
{
    float W[4][6];
    int off = r0 << 12;

    // prologue: rows r0-1 -> slot3, r0 -> slot0, r0+1 -> slot1
#pragma unroll
    for (int q = 0; q < 3; q++) {
        static const int slot[3] = { 3, 0, 1 };
        const int o = off + (q - 1) * IMG_W;
        const float4 v  = *reinterpret_cast<const float4*>(mag + o + x);
        const float  lv = __ldg(mag + o + xl) * lmask;
        const float  rv = __ldg(mag + o + xr) * rmask;
        extend6(W[slot[q]], v, lv, rv, lane0, lane31);
    }
    float4 O4 = __ldcs(reinterpret_cast<const float4*>(ori + off + x));

#pragma unroll 1
    for (int o = 0; o < H / 4; o++) {
#pragma unroll
        for (int k = 0; k < 4; k++) {
            // loads first: mag row r+2, ori row r+1 (offsets fold into LDG imm)
            const float4 v  = *reinterpret_cast<const float4*>(mag + off + 2 * IMG_W + x);
            const float  lv = __ldg(mag + off + 2 * IMG_W + xl) * lmask;
            const float  rv = __ldg(mag + off + 2 * IMG_W + xr) * rmask;
            const float4 oN = __ldcs(reinterpret_cast<const float4*>(ori + off + IMG_W + x));

            const float4 R = nms_row(W[(k + 3) & 3], W[k & 3], W[(k + 1) & 3], O4, sbias);
            __stcs(reinterpret_cast<float4*>(out + off + x), R);

            extend6(W[(k + 2) & 3], v, lv, rv, lane0, lane31);
            O4 = oN;
            off += IMG_W;
        }
    }
}

// slow path: first/last chunk, full row clamping + zero padding
__device__ __forceinline__ void march_slow(
    const float* __restrict__ mag, const float* __restrict__ ori,
    float* __restrict__ out, const float* sbias,
    int r0, int x, int xl, int xr, float lmask, float rmask,
    bool lane0, bool lane31)
{
    float W[4][6];

#pragma unroll
    for (int q = 0; q < 3; q++) {
        static const int slot[3] = { 3, 0, 1 };
        const int  row = r0 + q - 1;
        const int  rc  = min(max(row, 0), IMG_H - 1);
        const int  ro  = rc << 12;
        const float z  = ((unsigned)row < (unsigned)IMG_H) ? 1.f : 0.f;
        float4 v  = *reinterpret_cast<const float4*>(mag + ro + x);
        v.x *= z; v.y *= z; v.z *= z; v.w *= z;
        const float lv = __ldg(mag + ro + xl) * lmask * z;
        const float rv = __ldg(mag + ro + xr) * rmask * z;
        extend6(W[slot[q]], v, lv, rv, lane0, lane31);
    }
    float4 O4 = __ldcs(reinterpret_cast<const float4*>(ori + (r0 << 12) + x));

#pragma unroll 1
    for (int o = 0; o < H / 4; o++) {
#pragma unroll
        for (int k = 0; k < 4; k++) {
            const int r = r0 + o * 4 + k;

            const int  row2 = r + 2;
            const int  rc2  = min(max(row2, 0), IMG_H - 1);
            const int  ro2  = rc2 << 12;
            const float z   = ((unsigned)row2 < (unsigned)IMG_H) ? 1.f : 0.f;
            float4 v  = *reinterpret_cast<const float4*>(mag + ro2 + x);
            v.x *= z; v.y *= z; v.z *= z; v.w *= z;
            const float lv = __ldg(mag + ro2 + xl) * lmask * z;
            const float rv = __ldg(mag + ro2 + xr) * rmask * z;
            const int  rn  = min(max(r + 1, 0), IMG_H - 1);
            const float4 oN = __ldcs(reinterpret_cast<const float4*>(ori + (rn << 12) + x));

            if ((unsigned)r < (unsigned)IMG_H) {
                const float4 R = nms_row(W[(k + 3) & 3], W[k & 3], W[(k + 1) & 3], O4, sbias);
                __stcs(reinterpret_cast<float4*>(out + (r << 12) + x), R);
            }

            extend6(W[(k + 2) & 3], v, lv, rv, lane0, lane31);
            O4 = oN;
        }
    }
}

__global__ __launch_bounds__(256, 4) void nms_kernel(
    const float* __restrict__ mag,
    const float* __restrict__ ori,
    const float* __restrict__ bias,
    float* __restrict__ out)
{
    __shared__ float sbias[8];
    const int lane = threadIdx.x;
    const int wy   = threadIdx.y;
    if (wy == 0 && lane < 8) sbias[lane] = bias[lane];
    __syncthreads();

    const int task  = blockIdx.x * 8 + wy;          // 0..4703
    const int strip = task & (STRIPS - 1);
    const int chunk = task >> 5;                    // 0..146
    const int x0 = strip * 128;
    const int x  = x0 + lane * 4;
    const int r0 = chunk * H;

    const bool leftOK  = (x0 > 0);
    const bool rightOK = (x0 + 128 < IMG_W);
    const int  xl = leftOK  ? x0 - 1   : 0;
    const int  xr = rightOK ? x0 + 128 : IMG_W - 1;
    const float lmask = leftOK  ? 1.f : 0.f;
    const float rmask = rightOK ? 1.f : 0.f;
    const bool lane0  = (lane == 0);
    const bool lane31 = (lane == 31);

    // interior iff rows r0-1 .. r0+H+1 all in [0, IMG_H)
    if (chunk >= 1 && chunk <= 145)
        march_fast(mag, ori, out, sbias, r0, x, xl, xr, lmask, rmask, lane0, lane31);
    else
        march_slow(mag, ori, out, sbias, r0, x, xl, xr, lmask, rmask, lane0, lane31);
}

extern "C" void kernel_launch(void* const* d_in, const int* in_sizes, int n_in,
                              void* d_out, int out_size)
{
    const float* mag  = (const float*)d_in[0];   // grad_magnitude [1,1,4096,4096]
    const float* ori  = (const float*)d_in[1];   // grad_orientation
    // d_in[2] = weight [8,1,3,3] -- fixed directional filters, collapsed analytically
    const float* bias = (const float*)d_in[3];   // bias [8]
    float* out = (float*)d_out;

    dim3 block(32, 8);                            // 8 warp-strips per block
    nms_kernel<<<GRIDB, block>>>(mag, ori, bias, out);
}